// round 11
// baseline (speedup 1.0000x reference)
#include <cuda_runtime.h>

#define Bsz 4096
#define LAT 256
#define Hd  512
#define Ad  64
#define Ld  128
#define NSTEP (Ld - 1)
#define TCHUNK 63                        // timesteps of gi per chunk (2 chunks cover t=1..126)
#define GIROWS (TCHUNK * Bsz)            // 258048 rows per chunk

// ---------------- scratch (device globals; total ~2.68 GB .bss) ----------------
__device__ float g_t1[Bsz * Hd];
__device__ float g_t2[Bsz * Hd];
__device__ float g_h0[Bsz * Hd];
__device__ float g_Hall[(size_t)NSTEP * Bsz * Hd];          // 1.065 GB
__device__ float g_big[(size_t)GIROWS * 3 * Hd];            // 1.586 GB: gi chunk, later P1 (1.065 GB)
__device__ float g_gib[3 * Hd];                             // gi of BOS row (+b_ih)

// ---------------- packed f32x2 helpers (sm_103a FFMA2) ----------------
__device__ __forceinline__ unsigned long long pk2(float x) {
    unsigned int u = __float_as_uint(x);
    unsigned long long r;
    asm("mov.b64 %0, {%1, %1};" : "=l"(r) : "r"(u));
    return r;
}
__device__ __forceinline__ unsigned long long fma2(unsigned long long a,
                                                   unsigned long long b,
                                                   unsigned long long c) {
    unsigned long long d;
    asm("fma.rn.f32x2 %0, %1, %2, %3;" : "=l"(d) : "l"(a), "l"(b), "l"(c));
    return d;
}
__device__ __forceinline__ float2 up2(unsigned long long a) {
    unsigned int lo, hi;
    asm("mov.b64 {%0, %1}, %2;" : "=r"(lo), "=r"(hi) : "l"(a));
    return make_float2(__uint_as_float(lo), __uint_as_float(hi));
}
__device__ __forceinline__ float sigf(float x) { return 1.f / (1.f + expf(-x)); }

// ---------------- generic NT GEMM with 2-stage smem pipeline
// C[m,n] = act( sum_k A[m,k]*W[n,k] + bias[n] );  BM=128, BN=128, BK=16, 256 thr.
template <bool TANH>
__global__ __launch_bounds__(256, 2) void gemm_nt_kernel(
    const float* __restrict__ Amat, const float* __restrict__ Wmat,
    const float* __restrict__ bias, float* __restrict__ C,
    int M, int N, int K)
{
    __shared__ float As[2][16][132];
    __shared__ float Ws[2][16][132];

    const int tid = threadIdx.x;
    const int tx = tid & 15, ty = tid >> 4;
    const int m0 = blockIdx.y * 128, n0 = blockIdx.x * 128;
    const int lm = tid >> 2, lk = (tid & 3) * 4;
    const int ntiles = K >> 4;

    unsigned long long acc[8][4];
#pragma unroll
    for (int i = 0; i < 8; i++)
#pragma unroll
        for (int j = 0; j < 4; j++) acc[i][j] = 0ull;

    const float* Ap0 = Amat + (size_t)(m0 + lm) * K + lk;
    const float* Ap1 = Ap0 + (size_t)64 * K;
    const float* Wp0 = Wmat + (size_t)(n0 + lm) * K + lk;
    const float* Wp1 = Wp0 + (size_t)64 * K;

    float4 a0 = *(const float4*)(Ap0);
    float4 a1 = *(const float4*)(Ap1);
    float4 w0 = *(const float4*)(Wp0);
    float4 w1 = *(const float4*)(Wp1);
    As[0][lk + 0][lm] = a0.x; As[0][lk + 1][lm] = a0.y; As[0][lk + 2][lm] = a0.z; As[0][lk + 3][lm] = a0.w;
    As[0][lk + 0][lm + 64] = a1.x; As[0][lk + 1][lm + 64] = a1.y; As[0][lk + 2][lm + 64] = a1.z; As[0][lk + 3][lm + 64] = a1.w;
    Ws[0][lk + 0][lm] = w0.x; Ws[0][lk + 1][lm] = w0.y; Ws[0][lk + 2][lm] = w0.z; Ws[0][lk + 3][lm] = w0.w;
    Ws[0][lk + 0][lm + 64] = w1.x; Ws[0][lk + 1][lm + 64] = w1.y; Ws[0][lk + 2][lm + 64] = w1.z; Ws[0][lk + 3][lm + 64] = w1.w;
    __syncthreads();

    for (int kt = 0; kt < ntiles; kt++) {
        const int s = kt & 1;
        const bool more = (kt + 1 < ntiles);
        if (more) {
            int k0 = (kt + 1) * 16;
            a0 = *(const float4*)(Ap0 + k0);
            a1 = *(const float4*)(Ap1 + k0);
            w0 = *(const float4*)(Wp0 + k0);
            w1 = *(const float4*)(Wp1 + k0);
        }
#pragma unroll
        for (int k = 0; k < 16; k++) {
            float4 af0 = *(const float4*)&As[s][k][ty * 8];
            float4 af1 = *(const float4*)&As[s][k][ty * 8 + 4];
            ulonglong2 wv0 = *(const ulonglong2*)&Ws[s][k][tx * 8];
            ulonglong2 wv1 = *(const ulonglong2*)&Ws[s][k][tx * 8 + 4];
            float av[8] = {af0.x, af0.y, af0.z, af0.w, af1.x, af1.y, af1.z, af1.w};
            unsigned long long wp[4] = {wv0.x, wv0.y, wv1.x, wv1.y};
#pragma unroll
            for (int i = 0; i < 8; i++) {
                unsigned long long aa = pk2(av[i]);
#pragma unroll
                for (int jp = 0; jp < 4; jp++) acc[i][jp] = fma2(aa, wp[jp], acc[i][jp]);
            }
        }
        if (more) {
            const int d = s ^ 1;
            As[d][lk + 0][lm] = a0.x; As[d][lk + 1][lm] = a0.y; As[d][lk + 2][lm] = a0.z; As[d][lk + 3][lm] = a0.w;
            As[d][lk + 0][lm + 64] = a1.x; As[d][lk + 1][lm + 64] = a1.y; As[d][lk + 2][lm + 64] = a1.z; As[d][lk + 3][lm + 64] = a1.w;
            Ws[d][lk + 0][lm] = w0.x; Ws[d][lk + 1][lm] = w0.y; Ws[d][lk + 2][lm] = w0.z; Ws[d][lk + 3][lm] = w0.w;
            Ws[d][lk + 0][lm + 64] = w1.x; Ws[d][lk + 1][lm + 64] = w1.y; Ws[d][lk + 2][lm + 64] = w1.z; Ws[d][lk + 3][lm + 64] = w1.w;
        }
        __syncthreads();
    }

#pragma unroll
    for (int i = 0; i < 8; i++) {
        int row = m0 + ty * 8 + i;
        float* crow = C + (size_t)row * N + n0 + tx * 8;
#pragma unroll
        for (int jp = 0; jp < 4; jp++) {
            float2 v = up2(acc[i][jp]);
            int n = n0 + tx * 8 + jp * 2;
            v.x += bias[n];
            v.y += bias[n + 1];
            if (TANH) { v.x = tanhf(v.x); v.y = tanhf(v.y); }
            *(float2*)(crow + jp * 2) = v;
        }
    }
}

// ---------------- gi chunk GEMM: gi[(tl*Bsz + b)][n] = target[b][tbase+tl] @ W_ih^T + b_ih
// Same tiling/pipeline as gemm_nt; A rows gathered via (t,b) decode. K=64, N=1536.
__global__ __launch_bounds__(256, 2) void gi_gemm_kernel(
    const float* __restrict__ target, const float* __restrict__ W_ih,
    const float* __restrict__ b_ih, float* __restrict__ gi, int tbase)
{
    __shared__ float As[2][16][132];
    __shared__ float Ws[2][16][132];

    const int tid = threadIdx.x;
    const int tx = tid & 15, ty = tid >> 4;
    const int m0 = blockIdx.y * 128, n0 = blockIdx.x * 128;
    const int lm = tid >> 2, lk = (tid & 3) * 4;
    const int K = Ad, N = 3 * Hd, ntiles = Ad >> 4;

    unsigned long long acc[8][4];
#pragma unroll
    for (int i = 0; i < 8; i++)
#pragma unroll
        for (int j = 0; j < 4; j++) acc[i][j] = 0ull;

    const int mA0 = m0 + lm, mA1 = m0 + lm + 64;
    const float* Ap0 = target + ((size_t)(mA0 & 4095) * Ld + (tbase + (mA0 >> 12))) * Ad + lk;
    const float* Ap1 = target + ((size_t)(mA1 & 4095) * Ld + (tbase + (mA1 >> 12))) * Ad + lk;
    const float* Wp0 = W_ih + (size_t)(n0 + lm) * K + lk;
    const float* Wp1 = Wp0 + (size_t)64 * K;

    float4 a0 = *(const float4*)(Ap0);
    float4 a1 = *(const float4*)(Ap1);
    float4 w0 = *(const float4*)(Wp0);
    float4 w1 = *(const float4*)(Wp1);
    As[0][lk + 0][lm] = a0.x; As[0][lk + 1][lm] = a0.y; As[0][lk + 2][lm] = a0.z; As[0][lk + 3][lm] = a0.w;
    As[0][lk + 0][lm + 64] = a1.x; As[0][lk + 1][lm + 64] = a1.y; As[0][lk + 2][lm + 64] = a1.z; As[0][lk + 3][lm + 64] = a1.w;
    Ws[0][lk + 0][lm] = w0.x; Ws[0][lk + 1][lm] = w0.y; Ws[0][lk + 2][lm] = w0.z; Ws[0][lk + 3][lm] = w0.w;
    Ws[0][lk + 0][lm + 64] = w1.x; Ws[0][lk + 1][lm + 64] = w1.y; Ws[0][lk + 2][lm + 64] = w1.z; Ws[0][lk + 3][lm + 64] = w1.w;
    __syncthreads();

    for (int kt = 0; kt < ntiles; kt++) {
        const int s = kt & 1;
        const bool more = (kt + 1 < ntiles);
        if (more) {
            int k0 = (kt + 1) * 16;
            a0 = *(const float4*)(Ap0 + k0);
            a1 = *(const float4*)(Ap1 + k0);
            w0 = *(const float4*)(Wp0 + k0);
            w1 = *(const float4*)(Wp1 + k0);
        }
#pragma unroll
        for (int k = 0; k < 16; k++) {
            float4 af0 = *(const float4*)&As[s][k][ty * 8];
            float4 af1 = *(const float4*)&As[s][k][ty * 8 + 4];
            ulonglong2 wv0 = *(const ulonglong2*)&Ws[s][k][tx * 8];
            ulonglong2 wv1 = *(const ulonglong2*)&Ws[s][k][tx * 8 + 4];
            float av[8] = {af0.x, af0.y, af0.z, af0.w, af1.x, af1.y, af1.z, af1.w};
            unsigned long long wp[4] = {wv0.x, wv0.y, wv1.x, wv1.y};
#pragma unroll
            for (int i = 0; i < 8; i++) {
                unsigned long long aa = pk2(av[i]);
#pragma unroll
                for (int jp = 0; jp < 4; jp++) acc[i][jp] = fma2(aa, wp[jp], acc[i][jp]);
            }
        }
        if (more) {
            const int d = s ^ 1;
            As[d][lk + 0][lm] = a0.x; As[d][lk + 1][lm] = a0.y; As[d][lk + 2][lm] = a0.z; As[d][lk + 3][lm] = a0.w;
            As[d][lk + 0][lm + 64] = a1.x; As[d][lk + 1][lm + 64] = a1.y; As[d][lk + 2][lm + 64] = a1.z; As[d][lk + 3][lm + 64] = a1.w;
            Ws[d][lk + 0][lm] = w0.x; Ws[d][lk + 1][lm] = w0.y; Ws[d][lk + 2][lm] = w0.z; Ws[d][lk + 3][lm] = w0.w;
            Ws[d][lk + 0][lm + 64] = w1.x; Ws[d][lk + 1][lm + 64] = w1.y; Ws[d][lk + 2][lm + 64] = w1.z; Ws[d][lk + 3][lm + 64] = w1.w;
        }
        __syncthreads();
    }

#pragma unroll
    for (int i = 0; i < 8; i++) {
        int row = m0 + ty * 8 + i;
        float* crow = gi + (size_t)row * N + n0 + tx * 8;
#pragma unroll
        for (int jp = 0; jp < 4; jp++) {
            float2 v = up2(acc[i][jp]);
            int n = n0 + tx * 8 + jp * 2;
            v.x += b_ih[n];
            v.y += b_ih[n + 1];
            *(float2*)(crow + jp * 2) = v;
        }
    }
}

// ---------------- BOS input-gate vector: gib[n] = b_ih[n] - 16*sum_k W_ih[n,k] + 32*W_ih[n,0]
__global__ void gib_kernel(const float* __restrict__ W_ih, const float* __restrict__ b_ih,
                           float* __restrict__ gib) {
    int n = blockIdx.x * blockDim.x + threadIdx.x;
    if (n < 3 * Hd) {
        const float* w = W_ih + (size_t)n * Ad;
        float s = 0.f;
#pragma unroll
        for (int k = 0; k < Ad; k++) s += w[k];
        gib[n] = b_ih[n] - 16.f * s + 32.f * w[0];
    }
}

// ---------------- fused GRU step: hidden-gates GEMM (K=512) + gi epilogue + update
// Tile: 64 (batch) x 64 (hidden-unit j), 3 gate weight tiles, 4x4 microtile,
// 2-stage smem pipeline. gi (x@W_ih^T + b_ih) precomputed; tl = t_local in chunk.
__global__ __launch_bounds__(256, 2) void gru_step_kernel(
    const float* __restrict__ W_hh, const float* __restrict__ b_hh, int t, int tl)
{
    __shared__ float As[2][16][68];
    __shared__ float Wr[2][16][68];
    __shared__ float Wz[2][16][68];
    __shared__ float Wn[2][16][68];

    const float* hprev = (t == 0) ? g_h0 : (g_Hall + (size_t)(t - 1) * Bsz * Hd);
    float* hout = g_Hall + (size_t)t * Bsz * Hd;

    const int tid = threadIdx.x;
    const int tx = tid & 15, ty = tid >> 4;
    const int j0 = blockIdx.x * 64, m0 = blockIdx.y * 64;
    const int ln = tid >> 2, lk = (tid & 3) * 4;

    // gi pointer for this tile's rows
    const float* gi_ptr;
    size_t grs;   // per-row stride in floats
    if (t == 0) {
        gi_ptr = g_gib;
        grs = 0;
    } else {
        gi_ptr = g_big + ((size_t)tl * Bsz + m0) * (3 * Hd);
        grs = 3 * Hd;
    }

    unsigned long long ar[4][2], az[4][2], an[4][2];
#pragma unroll
    for (int i = 0; i < 4; i++)
#pragma unroll
        for (int j = 0; j < 2; j++) { ar[i][j] = 0ull; az[i][j] = 0ull; an[i][j] = 0ull; }

    const float* hp_l = hprev + (size_t)(m0 + ln) * Hd + lk;
    const float* wr_l = W_hh + (size_t)(j0 + ln) * Hd + lk;
    const float* wz_l = wr_l + (size_t)Hd * Hd;
    const float* wn_l = wz_l + (size_t)Hd * Hd;

    float4 av = *(const float4*)(hp_l);
    float4 r4 = *(const float4*)(wr_l);
    float4 z4 = *(const float4*)(wz_l);
    float4 n4 = *(const float4*)(wn_l);
    As[0][lk + 0][ln] = av.x; As[0][lk + 1][ln] = av.y; As[0][lk + 2][ln] = av.z; As[0][lk + 3][ln] = av.w;
    Wr[0][lk + 0][ln] = r4.x; Wr[0][lk + 1][ln] = r4.y; Wr[0][lk + 2][ln] = r4.z; Wr[0][lk + 3][ln] = r4.w;
    Wz[0][lk + 0][ln] = z4.x; Wz[0][lk + 1][ln] = z4.y; Wz[0][lk + 2][ln] = z4.z; Wz[0][lk + 3][ln] = z4.w;
    Wn[0][lk + 0][ln] = n4.x; Wn[0][lk + 1][ln] = n4.y; Wn[0][lk + 2][ln] = n4.z; Wn[0][lk + 3][ln] = n4.w;
    __syncthreads();

    for (int kt = 0; kt < 32; kt++) {
        const int s = kt & 1;
        const bool more = (kt < 31);
        if (more) {
            int k0 = (kt + 1) * 16;
            av = *(const float4*)(hp_l + k0);
            r4 = *(const float4*)(wr_l + k0);
            z4 = *(const float4*)(wz_l + k0);
            n4 = *(const float4*)(wn_l + k0);
        }
#pragma unroll
        for (int k = 0; k < 16; k++) {
            float4 af = *(const float4*)&As[s][k][ty * 4];
            ulonglong2 rw = *(const ulonglong2*)&Wr[s][k][tx * 4];
            ulonglong2 zw = *(const ulonglong2*)&Wz[s][k][tx * 4];
            ulonglong2 nw = *(const ulonglong2*)&Wn[s][k][tx * 4];
            float av4[4] = {af.x, af.y, af.z, af.w};
#pragma unroll
            for (int i = 0; i < 4; i++) {
                unsigned long long aa = pk2(av4[i]);
                ar[i][0] = fma2(aa, rw.x, ar[i][0]);  ar[i][1] = fma2(aa, rw.y, ar[i][1]);
                az[i][0] = fma2(aa, zw.x, az[i][0]);  az[i][1] = fma2(aa, zw.y, az[i][1]);
                an[i][0] = fma2(aa, nw.x, an[i][0]);  an[i][1] = fma2(aa, nw.y, an[i][1]);
            }
        }
        if (more) {
            const int d = s ^ 1;
            As[d][lk + 0][ln] = av.x; As[d][lk + 1][ln] = av.y; As[d][lk + 2][ln] = av.z; As[d][lk + 3][ln] = av.w;
            Wr[d][lk + 0][ln] = r4.x; Wr[d][lk + 1][ln] = r4.y; Wr[d][lk + 2][ln] = r4.z; Wr[d][lk + 3][ln] = r4.w;
            Wz[d][lk + 0][ln] = z4.x; Wz[d][lk + 1][ln] = z4.y; Wz[d][lk + 2][ln] = z4.z; Wz[d][lk + 3][ln] = z4.w;
            Wn[d][lk + 0][ln] = n4.x; Wn[d][lk + 1][ln] = n4.y; Wn[d][lk + 2][ln] = n4.z; Wn[d][lk + 3][ln] = n4.w;
        }
        __syncthreads();
    }

    // ---- GRU elementwise update epilogue (gi already contains x@W_ih^T + b_ih) ----
#pragma unroll
    for (int jp = 0; jp < 2; jp++) {
        int j = j0 + tx * 4 + jp * 2;
        float bhr0 = b_hh[j],          bhr1 = b_hh[j + 1];
        float bhz0 = b_hh[Hd + j],     bhz1 = b_hh[Hd + j + 1];
        float bhn0 = b_hh[2 * Hd + j], bhn1 = b_hh[2 * Hd + j + 1];
#pragma unroll
        for (int i = 0; i < 4; i++) {
            int row = m0 + ty * 4 + i;
            const float* gi_p = gi_ptr + (size_t)(ty * 4 + i) * grs;
            float2 gr = *(const float2*)(gi_p + j);
            float2 gz = *(const float2*)(gi_p + Hd + j);
            float2 gn = *(const float2*)(gi_p + 2 * Hd + j);
            float2 vr = up2(ar[i][jp]), vz = up2(az[i][jp]), vn = up2(an[i][jp]);
            float hp0 = hprev[(size_t)row * Hd + j];
            float hp1 = hprev[(size_t)row * Hd + j + 1];
            float r0 = sigf(vr.x + bhr0 + gr.x);
            float z0 = sigf(vz.x + bhz0 + gz.x);
            float nn0 = tanhf(gn.x + r0 * (vn.x + bhn0));
            float o0 = (1.f - z0) * nn0 + z0 * hp0;
            float r1 = sigf(vr.y + bhr1 + gr.y);
            float z1 = sigf(vz.y + bhz1 + gz.y);
            float nn1 = tanhf(gn.y + r1 * (vn.y + bhn1));
            float o1 = (1.f - z1) * nn1 + z1 * hp1;
            *(float2*)(hout + (size_t)row * Hd + j) = make_float2(o0, o1);
        }
    }
}

// ---------------- fused decoder tail: p2 = tanh(P1 @ Wm2^T + bm2); out = p2 @ Wm3^T + bm3
__global__ __launch_bounds__(256) void decode_tail_kernel(
    const float* __restrict__ P1,
    const float* __restrict__ Wm2, const float* __restrict__ bm2,
    const float* __restrict__ Wm3, const float* __restrict__ bm3,
    float* __restrict__ out)
{
    __shared__ float As[16][68];
    __shared__ float Ws[16][68];
    __shared__ float P2s[64][68];
    __shared__ float W3T[64][68];   // [k][n] = Wm3[n][k]

    const int tid = threadIdx.x;
    const int tx = tid & 15, ty = tid >> 4;
    const int m0 = blockIdx.x * 64;
    const int ln = tid >> 2, lk = (tid & 3) * 4;

#pragma unroll
    for (int r = 0; r < 16; r++) {
        int idx = tid + r * 256;
        int n = idx >> 6, k = idx & 63;
        W3T[k][n] = Wm3[n * 64 + k];
    }

    unsigned long long acc[4][2];
#pragma unroll
    for (int i = 0; i < 4; i++) { acc[i][0] = 0ull; acc[i][1] = 0ull; }

    const float* a_l = P1 + (size_t)(m0 + ln) * Hd + lk;
    const float* w_l = Wm2 + (size_t)ln * Hd + lk;
    for (int kt = 0; kt < 32; kt++) {
        int k0 = kt * 16;
        float4 av = *(const float4*)(a_l + k0);
        float4 wv = *(const float4*)(w_l + k0);
        As[lk + 0][ln] = av.x; As[lk + 1][ln] = av.y; As[lk + 2][ln] = av.z; As[lk + 3][ln] = av.w;
        Ws[lk + 0][ln] = wv.x; Ws[lk + 1][ln] = wv.y; Ws[lk + 2][ln] = wv.z; Ws[lk + 3][ln] = wv.w;
        __syncthreads();
#pragma unroll
        for (int k = 0; k < 16; k++) {
            float4 af = *(const float4*)&As[k][ty * 4];
            ulonglong2 ww = *(const ulonglong2*)&Ws[k][tx * 4];
            float av4[4] = {af.x, af.y, af.z, af.w};
#pragma unroll
            for (int i = 0; i < 4; i++) {
                unsigned long long aa = pk2(av4[i]);
                acc[i][0] = fma2(aa, ww.x, acc[i][0]);
                acc[i][1] = fma2(aa, ww.y, acc[i][1]);
            }
        }
        __syncthreads();
    }

#pragma unroll
    for (int i = 0; i < 4; i++) {
#pragma unroll
        for (int jp = 0; jp < 2; jp++) {
            float2 v = up2(acc[i][jp]);
            int n = tx * 4 + jp * 2;
            v.x = tanhf(v.x + bm2[n]);
            v.y = tanhf(v.y + bm2[n + 1]);
            *(float2*)&P2s[ty * 4 + i][n] = v;
        }
    }
    __syncthreads();

    unsigned long long a2[4][2];
#pragma unroll
    for (int i = 0; i < 4; i++) { a2[i][0] = 0ull; a2[i][1] = 0ull; }
#pragma unroll 8
    for (int k = 0; k < 64; k++) {
        ulonglong2 wv = *(const ulonglong2*)&W3T[k][tx * 4];
#pragma unroll
        for (int i = 0; i < 4; i++) {
            unsigned long long aa = pk2(P2s[ty * 4 + i][k]);
            a2[i][0] = fma2(aa, wv.x, a2[i][0]);
            a2[i][1] = fma2(aa, wv.y, a2[i][1]);
        }
    }

#pragma unroll
    for (int i = 0; i < 4; i++) {
        int m = m0 + ty * 4 + i;
        int t = m >> 12;          // row = t*B + b, B = 4096
        int b = m & 4095;
        float* orow = out + (size_t)b * (Ld * Ad) + (size_t)(t + 1) * Ad;
#pragma unroll
        for (int jp = 0; jp < 2; jp++) {
            float2 v = up2(a2[i][jp]);
            int n = tx * 4 + jp * 2;
            v.x += bm3[n];
            v.y += bm3[n + 1];
            *(float2*)(orow + n) = v;
        }
    }
}

__global__ void bos_kernel(float* __restrict__ out) {
    int i = blockIdx.x * blockDim.x + threadIdx.x;
    if (i < Bsz * Ad) {
        int b = i >> 6, a = i & 63;
        out[(size_t)b * (Ld * Ad) + a] = (a == 0) ? 16.f : -16.f;
    }
}

// ---------------- launcher ----------------
extern "C" void kernel_launch(void* const* d_in, const int* in_sizes, int n_in,
                              void* d_out, int out_size)
{
    const float* latent = (const float*)d_in[0];
    const float* target = (const float*)d_in[1];
    const float* Wd1 = (const float*)d_in[2];  const float* bd1 = (const float*)d_in[3];
    const float* Wd2 = (const float*)d_in[4];  const float* bd2 = (const float*)d_in[5];
    const float* Wd3 = (const float*)d_in[6];  const float* bd3 = (const float*)d_in[7];
    const float* W_ih = (const float*)d_in[8]; const float* W_hh = (const float*)d_in[9];
    const float* b_ih = (const float*)d_in[10]; const float* b_hh = (const float*)d_in[11];
    const float* Wm1 = (const float*)d_in[12]; const float* bm1 = (const float*)d_in[13];
    const float* Wm2 = (const float*)d_in[14]; const float* bm2 = (const float*)d_in[15];
    const float* Wm3 = (const float*)d_in[16]; const float* bm3 = (const float*)d_in[17];
    float* out = (float*)d_out;

    float *t1p, *t2p, *h0p, *Hallp, *bigp, *gibp;
    cudaGetSymbolAddress((void**)&t1p, g_t1);
    cudaGetSymbolAddress((void**)&t2p, g_t2);
    cudaGetSymbolAddress((void**)&h0p, g_h0);
    cudaGetSymbolAddress((void**)&Hallp, g_Hall);
    cudaGetSymbolAddress((void**)&bigp, g_big);
    cudaGetSymbolAddress((void**)&gibp, g_gib);

    dim3 thr(256);

    // BOS input-gate vector (includes b_ih)
    gib_kernel<<<(3 * Hd + 255) / 256, 256>>>(W_ih, b_ih, gibp);

    // gi chunk 0: t in [1, 63]
    gi_gemm_kernel<<<dim3((3 * Hd) / 128, GIROWS / 128), thr>>>(target, W_ih, b_ih, bigp, 1);

    // initial hidden MLP
    gemm_nt_kernel<true><<<dim3(Hd / 128, Bsz / 128), thr>>>(latent, Wd1, bd1, t1p, Bsz, Hd, LAT);
    gemm_nt_kernel<true><<<dim3(Hd / 128, Bsz / 128), thr>>>(t1p, Wd2, bd2, t2p, Bsz, Hd, Hd);
    gemm_nt_kernel<false><<<dim3(Hd / 128, Bsz / 128), thr>>>(t2p, Wd3, bd3, h0p, Bsz, Hd, Hd);

    // sequential GRU steps: t=0 (BOS) .. 63 use chunk 0
    for (int t = 0; t <= TCHUNK; t++) {
        gru_step_kernel<<<dim3(Hd / 64, Bsz / 64), thr>>>(W_hh, b_hh, t, t - 1);
    }
    // gi chunk 1: t in [64, 126] (overwrites chunk 0 — stream order makes this safe)
    gi_gemm_kernel<<<dim3((3 * Hd) / 128, GIROWS / 128), thr>>>(target, W_ih, b_ih, bigp, 1 + TCHUNK);
    for (int t = TCHUNK + 1; t < NSTEP; t++) {
        gru_step_kernel<<<dim3(Hd / 64, Bsz / 64), thr>>>(W_hh, b_hh, t, t - 1 - TCHUNK);
    }

    // batched decoder head over all (t, b) rows; P1 aliases the gi buffer (gi is dead)
    gemm_nt_kernel<true><<<dim3(Hd / 128, (NSTEP * Bsz) / 128), thr>>>(
        Hallp, Wm1, bm1, bigp, NSTEP * Bsz, Hd, Hd);
    decode_tail_kernel<<<dim3((NSTEP * Bsz) / 64), thr>>>(bigp, Wm2, bm2, Wm3, bm3, out);

    // BOS column (out[:, 0, :])
    bos_kernel<<<(Bsz * Ad + 255) / 256, 256>>>(out);
}

// round 12
// speedup vs baseline: 1.0021x; 1.0021x over previous
#include <cuda_runtime.h>

#define Bsz 4096
#define LAT 256
#define Hd  512
#define Ad  64
#define Ld  128
#define NSTEP (Ld - 1)
#define TCHUNK 63                        // timesteps of gi per chunk (2 chunks cover t=1..126)
#define GIROWS (TCHUNK * Bsz)            // 258048 rows per chunk

// ---------------- scratch (device globals; total ~2.68 GB .bss) ----------------
__device__ float g_t1[Bsz * Hd];
__device__ float g_t2[Bsz * Hd];
__device__ float g_h0[Bsz * Hd];
__device__ float g_Hall[(size_t)NSTEP * Bsz * Hd];          // 1.065 GB
__device__ float g_big[(size_t)GIROWS * 3 * Hd];            // 1.586 GB: gi chunk, later P1 (1.065 GB)
__device__ float g_gib[3 * Hd];                             // gi of BOS row (+b_ih)

// ---------------- packed f32x2 helpers (sm_103a FFMA2) ----------------
__device__ __forceinline__ unsigned long long pk2(float x) {
    unsigned int u = __float_as_uint(x);
    unsigned long long r;
    asm("mov.b64 %0, {%1, %1};" : "=l"(r) : "r"(u));
    return r;
}
__device__ __forceinline__ unsigned long long fma2(unsigned long long a,
                                                   unsigned long long b,
                                                   unsigned long long c) {
    unsigned long long d;
    asm("fma.rn.f32x2 %0, %1, %2, %3;" : "=l"(d) : "l"(a), "l"(b), "l"(c));
    return d;
}
__device__ __forceinline__ float2 up2(unsigned long long a) {
    unsigned int lo, hi;
    asm("mov.b64 {%0, %1}, %2;" : "=r"(lo), "=r"(hi) : "l"(a));
    return make_float2(__uint_as_float(lo), __uint_as_float(hi));
}
__device__ __forceinline__ float sigf(float x) { return 1.f / (1.f + expf(-x)); }

// ---------------- generic NT GEMM with 2-stage smem pipeline
// C[m,n] = act( sum_k A[m,k]*W[n,k] + bias[n] );  BM=128, BN=128, BK=16, 256 thr.
template <bool TANH>
__global__ __launch_bounds__(256, 2) void gemm_nt_kernel(
    const float* __restrict__ Amat, const float* __restrict__ Wmat,
    const float* __restrict__ bias, float* __restrict__ C,
    int M, int N, int K)
{
    __shared__ float As[2][16][132];
    __shared__ float Ws[2][16][132];

    const int tid = threadIdx.x;
    const int tx = tid & 15, ty = tid >> 4;
    const int m0 = blockIdx.y * 128, n0 = blockIdx.x * 128;
    const int lm = tid >> 2, lk = (tid & 3) * 4;
    const int ntiles = K >> 4;

    unsigned long long acc[8][4];
#pragma unroll
    for (int i = 0; i < 8; i++)
#pragma unroll
        for (int j = 0; j < 4; j++) acc[i][j] = 0ull;

    const float* Ap0 = Amat + (size_t)(m0 + lm) * K + lk;
    const float* Ap1 = Ap0 + (size_t)64 * K;
    const float* Wp0 = Wmat + (size_t)(n0 + lm) * K + lk;
    const float* Wp1 = Wp0 + (size_t)64 * K;

    float4 a0 = *(const float4*)(Ap0);
    float4 a1 = *(const float4*)(Ap1);
    float4 w0 = *(const float4*)(Wp0);
    float4 w1 = *(const float4*)(Wp1);
    As[0][lk + 0][lm] = a0.x; As[0][lk + 1][lm] = a0.y; As[0][lk + 2][lm] = a0.z; As[0][lk + 3][lm] = a0.w;
    As[0][lk + 0][lm + 64] = a1.x; As[0][lk + 1][lm + 64] = a1.y; As[0][lk + 2][lm + 64] = a1.z; As[0][lk + 3][lm + 64] = a1.w;
    Ws[0][lk + 0][lm] = w0.x; Ws[0][lk + 1][lm] = w0.y; Ws[0][lk + 2][lm] = w0.z; Ws[0][lk + 3][lm] = w0.w;
    Ws[0][lk + 0][lm + 64] = w1.x; Ws[0][lk + 1][lm + 64] = w1.y; Ws[0][lk + 2][lm + 64] = w1.z; Ws[0][lk + 3][lm + 64] = w1.w;
    __syncthreads();

    for (int kt = 0; kt < ntiles; kt++) {
        const int s = kt & 1;
        const bool more = (kt + 1 < ntiles);
        if (more) {
            int k0 = (kt + 1) * 16;
            a0 = *(const float4*)(Ap0 + k0);
            a1 = *(const float4*)(Ap1 + k0);
            w0 = *(const float4*)(Wp0 + k0);
            w1 = *(const float4*)(Wp1 + k0);
        }
#pragma unroll
        for (int k = 0; k < 16; k++) {
            float4 af0 = *(const float4*)&As[s][k][ty * 8];
            float4 af1 = *(const float4*)&As[s][k][ty * 8 + 4];
            ulonglong2 wv0 = *(const ulonglong2*)&Ws[s][k][tx * 8];
            ulonglong2 wv1 = *(const ulonglong2*)&Ws[s][k][tx * 8 + 4];
            float av[8] = {af0.x, af0.y, af0.z, af0.w, af1.x, af1.y, af1.z, af1.w};
            unsigned long long wp[4] = {wv0.x, wv0.y, wv1.x, wv1.y};
#pragma unroll
            for (int i = 0; i < 8; i++) {
                unsigned long long aa = pk2(av[i]);
#pragma unroll
                for (int jp = 0; jp < 4; jp++) acc[i][jp] = fma2(aa, wp[jp], acc[i][jp]);
            }
        }
        if (more) {
            const int d = s ^ 1;
            As[d][lk + 0][lm] = a0.x; As[d][lk + 1][lm] = a0.y; As[d][lk + 2][lm] = a0.z; As[d][lk + 3][lm] = a0.w;
            As[d][lk + 0][lm + 64] = a1.x; As[d][lk + 1][lm + 64] = a1.y; As[d][lk + 2][lm + 64] = a1.z; As[d][lk + 3][lm + 64] = a1.w;
            Ws[d][lk + 0][lm] = w0.x; Ws[d][lk + 1][lm] = w0.y; Ws[d][lk + 2][lm] = w0.z; Ws[d][lk + 3][lm] = w0.w;
            Ws[d][lk + 0][lm + 64] = w1.x; Ws[d][lk + 1][lm + 64] = w1.y; Ws[d][lk + 2][lm + 64] = w1.z; Ws[d][lk + 3][lm + 64] = w1.w;
        }
        __syncthreads();
    }

#pragma unroll
    for (int i = 0; i < 8; i++) {
        int row = m0 + ty * 8 + i;
        float* crow = C + (size_t)row * N + n0 + tx * 8;
#pragma unroll
        for (int jp = 0; jp < 4; jp++) {
            float2 v = up2(acc[i][jp]);
            int n = n0 + tx * 8 + jp * 2;
            v.x += bias[n];
            v.y += bias[n + 1];
            if (TANH) { v.x = tanhf(v.x); v.y = tanhf(v.y); }
            *(float2*)(crow + jp * 2) = v;
        }
    }
}

// ---------------- gi chunk GEMM: gi[(tl*Bsz + b)][n] = target[b][tbase+tl] @ W_ih^T + b_ih
// Same tiling/pipeline as gemm_nt; A rows gathered via (t,b) decode. K=64, N=1536.
__global__ __launch_bounds__(256, 2) void gi_gemm_kernel(
    const float* __restrict__ target, const float* __restrict__ W_ih,
    const float* __restrict__ b_ih, float* __restrict__ gi, int tbase)
{
    __shared__ float As[2][16][132];
    __shared__ float Ws[2][16][132];

    const int tid = threadIdx.x;
    const int tx = tid & 15, ty = tid >> 4;
    const int m0 = blockIdx.y * 128, n0 = blockIdx.x * 128;
    const int lm = tid >> 2, lk = (tid & 3) * 4;
    const int K = Ad, N = 3 * Hd, ntiles = Ad >> 4;

    unsigned long long acc[8][4];
#pragma unroll
    for (int i = 0; i < 8; i++)
#pragma unroll
        for (int j = 0; j < 4; j++) acc[i][j] = 0ull;

    const int mA0 = m0 + lm, mA1 = m0 + lm + 64;
    const float* Ap0 = target + ((size_t)(mA0 & 4095) * Ld + (tbase + (mA0 >> 12))) * Ad + lk;
    const float* Ap1 = target + ((size_t)(mA1 & 4095) * Ld + (tbase + (mA1 >> 12))) * Ad + lk;
    const float* Wp0 = W_ih + (size_t)(n0 + lm) * K + lk;
    const float* Wp1 = Wp0 + (size_t)64 * K;

    float4 a0 = *(const float4*)(Ap0);
    float4 a1 = *(const float4*)(Ap1);
    float4 w0 = *(const float4*)(Wp0);
    float4 w1 = *(const float4*)(Wp1);
    As[0][lk + 0][lm] = a0.x; As[0][lk + 1][lm] = a0.y; As[0][lk + 2][lm] = a0.z; As[0][lk + 3][lm] = a0.w;
    As[0][lk + 0][lm + 64] = a1.x; As[0][lk + 1][lm + 64] = a1.y; As[0][lk + 2][lm + 64] = a1.z; As[0][lk + 3][lm + 64] = a1.w;
    Ws[0][lk + 0][lm] = w0.x; Ws[0][lk + 1][lm] = w0.y; Ws[0][lk + 2][lm] = w0.z; Ws[0][lk + 3][lm] = w0.w;
    Ws[0][lk + 0][lm + 64] = w1.x; Ws[0][lk + 1][lm + 64] = w1.y; Ws[0][lk + 2][lm + 64] = w1.z; Ws[0][lk + 3][lm + 64] = w1.w;
    __syncthreads();

    for (int kt = 0; kt < ntiles; kt++) {
        const int s = kt & 1;
        const bool more = (kt + 1 < ntiles);
        if (more) {
            int k0 = (kt + 1) * 16;
            a0 = *(const float4*)(Ap0 + k0);
            a1 = *(const float4*)(Ap1 + k0);
            w0 = *(const float4*)(Wp0 + k0);
            w1 = *(const float4*)(Wp1 + k0);
        }
#pragma unroll
        for (int k = 0; k < 16; k++) {
            float4 af0 = *(const float4*)&As[s][k][ty * 8];
            float4 af1 = *(const float4*)&As[s][k][ty * 8 + 4];
            ulonglong2 wv0 = *(const ulonglong2*)&Ws[s][k][tx * 8];
            ulonglong2 wv1 = *(const ulonglong2*)&Ws[s][k][tx * 8 + 4];
            float av[8] = {af0.x, af0.y, af0.z, af0.w, af1.x, af1.y, af1.z, af1.w};
            unsigned long long wp[4] = {wv0.x, wv0.y, wv1.x, wv1.y};
#pragma unroll
            for (int i = 0; i < 8; i++) {
                unsigned long long aa = pk2(av[i]);
#pragma unroll
                for (int jp = 0; jp < 4; jp++) acc[i][jp] = fma2(aa, wp[jp], acc[i][jp]);
            }
        }
        if (more) {
            const int d = s ^ 1;
            As[d][lk + 0][lm] = a0.x; As[d][lk + 1][lm] = a0.y; As[d][lk + 2][lm] = a0.z; As[d][lk + 3][lm] = a0.w;
            As[d][lk + 0][lm + 64] = a1.x; As[d][lk + 1][lm + 64] = a1.y; As[d][lk + 2][lm + 64] = a1.z; As[d][lk + 3][lm + 64] = a1.w;
            Ws[d][lk + 0][lm] = w0.x; Ws[d][lk + 1][lm] = w0.y; Ws[d][lk + 2][lm] = w0.z; Ws[d][lk + 3][lm] = w0.w;
            Ws[d][lk + 0][lm + 64] = w1.x; Ws[d][lk + 1][lm + 64] = w1.y; Ws[d][lk + 2][lm + 64] = w1.z; Ws[d][lk + 3][lm + 64] = w1.w;
        }
        __syncthreads();
    }

#pragma unroll
    for (int i = 0; i < 8; i++) {
        int row = m0 + ty * 8 + i;
        float* crow = gi + (size_t)row * N + n0 + tx * 8;
#pragma unroll
        for (int jp = 0; jp < 4; jp++) {
            float2 v = up2(acc[i][jp]);
            int n = n0 + tx * 8 + jp * 2;
            v.x += b_ih[n];
            v.y += b_ih[n + 1];
            *(float2*)(crow + jp * 2) = v;
        }
    }
}

// ---------------- BOS input-gate vector: gib[n] = b_ih[n] - 16*sum_k W_ih[n,k] + 32*W_ih[n,0]
__global__ void gib_kernel(const float* __restrict__ W_ih, const float* __restrict__ b_ih,
                           float* __restrict__ gib) {
    int n = blockIdx.x * blockDim.x + threadIdx.x;
    if (n < 3 * Hd) {
        const float* w = W_ih + (size_t)n * Ad;
        float s = 0.f;
#pragma unroll
        for (int k = 0; k < Ad; k++) s += w[k];
        gib[n] = b_ih[n] - 16.f * s + 32.f * w[0];
    }
}

// ---------------- fused GRU step: hidden-gates GEMM (K=512) + gi epilogue + update
// Tile: 64 (batch) x 64 (hidden-unit j), 3 gate weight tiles, 4x4 microtile,
// 2-stage smem pipeline. gi (x@W_ih^T + b_ih) precomputed; tl = t_local in chunk.
__global__ __launch_bounds__(256, 2) void gru_step_kernel(
    const float* __restrict__ W_hh, const float* __restrict__ b_hh, int t, int tl)
{
    __shared__ float As[2][16][68];
    __shared__ float Wr[2][16][68];
    __shared__ float Wz[2][16][68];
    __shared__ float Wn[2][16][68];

    const float* hprev = (t == 0) ? g_h0 : (g_Hall + (size_t)(t - 1) * Bsz * Hd);
    float* hout = g_Hall + (size_t)t * Bsz * Hd;

    const int tid = threadIdx.x;
    const int tx = tid & 15, ty = tid >> 4;
    const int j0 = blockIdx.x * 64, m0 = blockIdx.y * 64;
    const int ln = tid >> 2, lk = (tid & 3) * 4;

    // gi pointer for this tile's rows
    const float* gi_ptr;
    size_t grs;   // per-row stride in floats
    if (t == 0) {
        gi_ptr = g_gib;
        grs = 0;
    } else {
        gi_ptr = g_big + ((size_t)tl * Bsz + m0) * (3 * Hd);
        grs = 3 * Hd;
    }

    unsigned long long ar[4][2], az[4][2], an[4][2];
#pragma unroll
    for (int i = 0; i < 4; i++)
#pragma unroll
        for (int j = 0; j < 2; j++) { ar[i][j] = 0ull; az[i][j] = 0ull; an[i][j] = 0ull; }

    const float* hp_l = hprev + (size_t)(m0 + ln) * Hd + lk;
    const float* wr_l = W_hh + (size_t)(j0 + ln) * Hd + lk;
    const float* wz_l = wr_l + (size_t)Hd * Hd;
    const float* wn_l = wz_l + (size_t)Hd * Hd;

    float4 av = *(const float4*)(hp_l);
    float4 r4 = *(const float4*)(wr_l);
    float4 z4 = *(const float4*)(wz_l);
    float4 n4 = *(const float4*)(wn_l);
    As[0][lk + 0][ln] = av.x; As[0][lk + 1][ln] = av.y; As[0][lk + 2][ln] = av.z; As[0][lk + 3][ln] = av.w;
    Wr[0][lk + 0][ln] = r4.x; Wr[0][lk + 1][ln] = r4.y; Wr[0][lk + 2][ln] = r4.z; Wr[0][lk + 3][ln] = r4.w;
    Wz[0][lk + 0][ln] = z4.x; Wz[0][lk + 1][ln] = z4.y; Wz[0][lk + 2][ln] = z4.z; Wz[0][lk + 3][ln] = z4.w;
    Wn[0][lk + 0][ln] = n4.x; Wn[0][lk + 1][ln] = n4.y; Wn[0][lk + 2][ln] = n4.z; Wn[0][lk + 3][ln] = n4.w;
    __syncthreads();

    for (int kt = 0; kt < 32; kt++) {
        const int s = kt & 1;
        const bool more = (kt < 31);
        if (more) {
            int k0 = (kt + 1) * 16;
            av = *(const float4*)(hp_l + k0);
            r4 = *(const float4*)(wr_l + k0);
            z4 = *(const float4*)(wz_l + k0);
            n4 = *(const float4*)(wn_l + k0);
        }
#pragma unroll
        for (int k = 0; k < 16; k++) {
            float4 af = *(const float4*)&As[s][k][ty * 4];
            ulonglong2 rw = *(const ulonglong2*)&Wr[s][k][tx * 4];
            ulonglong2 zw = *(const ulonglong2*)&Wz[s][k][tx * 4];
            ulonglong2 nw = *(const ulonglong2*)&Wn[s][k][tx * 4];
            float av4[4] = {af.x, af.y, af.z, af.w};
#pragma unroll
            for (int i = 0; i < 4; i++) {
                unsigned long long aa = pk2(av4[i]);
                ar[i][0] = fma2(aa, rw.x, ar[i][0]);  ar[i][1] = fma2(aa, rw.y, ar[i][1]);
                az[i][0] = fma2(aa, zw.x, az[i][0]);  az[i][1] = fma2(aa, zw.y, az[i][1]);
                an[i][0] = fma2(aa, nw.x, an[i][0]);  an[i][1] = fma2(aa, nw.y, an[i][1]);
            }
        }
        if (more) {
            const int d = s ^ 1;
            As[d][lk + 0][ln] = av.x; As[d][lk + 1][ln] = av.y; As[d][lk + 2][ln] = av.z; As[d][lk + 3][ln] = av.w;
            Wr[d][lk + 0][ln] = r4.x; Wr[d][lk + 1][ln] = r4.y; Wr[d][lk + 2][ln] = r4.z; Wr[d][lk + 3][ln] = r4.w;
            Wz[d][lk + 0][ln] = z4.x; Wz[d][lk + 1][ln] = z4.y; Wz[d][lk + 2][ln] = z4.z; Wz[d][lk + 3][ln] = z4.w;
            Wn[d][lk + 0][ln] = n4.x; Wn[d][lk + 1][ln] = n4.y; Wn[d][lk + 2][ln] = n4.z; Wn[d][lk + 3][ln] = n4.w;
        }
        __syncthreads();
    }

    // ---- GRU elementwise update epilogue (gi already contains x@W_ih^T + b_ih) ----
#pragma unroll
    for (int jp = 0; jp < 2; jp++) {
        int j = j0 + tx * 4 + jp * 2;
        float bhr0 = b_hh[j],          bhr1 = b_hh[j + 1];
        float bhz0 = b_hh[Hd + j],     bhz1 = b_hh[Hd + j + 1];
        float bhn0 = b_hh[2 * Hd + j], bhn1 = b_hh[2 * Hd + j + 1];
#pragma unroll
        for (int i = 0; i < 4; i++) {
            int row = m0 + ty * 4 + i;
            const float* gi_p = gi_ptr + (size_t)(ty * 4 + i) * grs;
            float2 gr = *(const float2*)(gi_p + j);
            float2 gz = *(const float2*)(gi_p + Hd + j);
            float2 gn = *(const float2*)(gi_p + 2 * Hd + j);
            float2 vr = up2(ar[i][jp]), vz = up2(az[i][jp]), vn = up2(an[i][jp]);
            float hp0 = hprev[(size_t)row * Hd + j];
            float hp1 = hprev[(size_t)row * Hd + j + 1];
            float r0 = sigf(vr.x + bhr0 + gr.x);
            float z0 = sigf(vz.x + bhz0 + gz.x);
            float nn0 = tanhf(gn.x + r0 * (vn.x + bhn0));
            float o0 = (1.f - z0) * nn0 + z0 * hp0;
            float r1 = sigf(vr.y + bhr1 + gr.y);
            float z1 = sigf(vz.y + bhz1 + gz.y);
            float nn1 = tanhf(gn.y + r1 * (vn.y + bhn1));
            float o1 = (1.f - z1) * nn1 + z1 * hp1;
            *(float2*)(hout + (size_t)row * Hd + j) = make_float2(o0, o1);
        }
    }
}

// ---------------- fused decoder tail: p2 = tanh(P1 @ Wm2^T + bm2); out = p2 @ Wm3^T + bm3
__global__ __launch_bounds__(256) void decode_tail_kernel(
    const float* __restrict__ P1,
    const float* __restrict__ Wm2, const float* __restrict__ bm2,
    const float* __restrict__ Wm3, const float* __restrict__ bm3,
    float* __restrict__ out)
{
    __shared__ float As[16][68];
    __shared__ float Ws[16][68];
    __shared__ float P2s[64][68];
    __shared__ float W3T[64][68];   // [k][n] = Wm3[n][k]

    const int tid = threadIdx.x;
    const int tx = tid & 15, ty = tid >> 4;
    const int m0 = blockIdx.x * 64;
    const int ln = tid >> 2, lk = (tid & 3) * 4;

#pragma unroll
    for (int r = 0; r < 16; r++) {
        int idx = tid + r * 256;
        int n = idx >> 6, k = idx & 63;
        W3T[k][n] = Wm3[n * 64 + k];
    }

    unsigned long long acc[4][2];
#pragma unroll
    for (int i = 0; i < 4; i++) { acc[i][0] = 0ull; acc[i][1] = 0ull; }

    const float* a_l = P1 + (size_t)(m0 + ln) * Hd + lk;
    const float* w_l = Wm2 + (size_t)ln * Hd + lk;
    for (int kt = 0; kt < 32; kt++) {
        int k0 = kt * 16;
        float4 av = *(const float4*)(a_l + k0);
        float4 wv = *(const float4*)(w_l + k0);
        As[lk + 0][ln] = av.x; As[lk + 1][ln] = av.y; As[lk + 2][ln] = av.z; As[lk + 3][ln] = av.w;
        Ws[lk + 0][ln] = wv.x; Ws[lk + 1][ln] = wv.y; Ws[lk + 2][ln] = wv.z; Ws[lk + 3][ln] = wv.w;
        __syncthreads();
#pragma unroll
        for (int k = 0; k < 16; k++) {
            float4 af = *(const float4*)&As[k][ty * 4];
            ulonglong2 ww = *(const ulonglong2*)&Ws[k][tx * 4];
            float av4[4] = {af.x, af.y, af.z, af.w};
#pragma unroll
            for (int i = 0; i < 4; i++) {
                unsigned long long aa = pk2(av4[i]);
                acc[i][0] = fma2(aa, ww.x, acc[i][0]);
                acc[i][1] = fma2(aa, ww.y, acc[i][1]);
            }
        }
        __syncthreads();
    }

#pragma unroll
    for (int i = 0; i < 4; i++) {
#pragma unroll
        for (int jp = 0; jp < 2; jp++) {
            float2 v = up2(acc[i][jp]);
            int n = tx * 4 + jp * 2;
            v.x = tanhf(v.x + bm2[n]);
            v.y = tanhf(v.y + bm2[n + 1]);
            *(float2*)&P2s[ty * 4 + i][n] = v;
        }
    }
    __syncthreads();

    unsigned long long a2[4][2];
#pragma unroll
    for (int i = 0; i < 4; i++) { a2[i][0] = 0ull; a2[i][1] = 0ull; }
#pragma unroll 8
    for (int k = 0; k < 64; k++) {
        ulonglong2 wv = *(const ulonglong2*)&W3T[k][tx * 4];
#pragma unroll
        for (int i = 0; i < 4; i++) {
            unsigned long long aa = pk2(P2s[ty * 4 + i][k]);
            a2[i][0] = fma2(aa, wv.x, a2[i][0]);
            a2[i][1] = fma2(aa, wv.y, a2[i][1]);
        }
    }

#pragma unroll
    for (int i = 0; i < 4; i++) {
        int m = m0 + ty * 4 + i;
        int t = m >> 12;          // row = t*B + b, B = 4096
        int b = m & 4095;
        float* orow = out + (size_t)b * (Ld * Ad) + (size_t)(t + 1) * Ad;
#pragma unroll
        for (int jp = 0; jp < 2; jp++) {
            float2 v = up2(a2[i][jp]);
            int n = tx * 4 + jp * 2;
            v.x += bm3[n];
            v.y += bm3[n + 1];
            *(float2*)(orow + n) = v;
        }
    }
}

__global__ void bos_kernel(float* __restrict__ out) {
    int i = blockIdx.x * blockDim.x + threadIdx.x;
    if (i < Bsz * Ad) {
        int b = i >> 6, a = i & 63;
        out[(size_t)b * (Ld * Ad) + a] = (a == 0) ? 16.f : -16.f;
    }
}

// ---------------- launcher ----------------
extern "C" void kernel_launch(void* const* d_in, const int* in_sizes, int n_in,
                              void* d_out, int out_size)
{
    const float* latent = (const float*)d_in[0];
    const float* target = (const float*)d_in[1];
    const float* Wd1 = (const float*)d_in[2];  const float* bd1 = (const float*)d_in[3];
    const float* Wd2 = (const float*)d_in[4];  const float* bd2 = (const float*)d_in[5];
    const float* Wd3 = (const float*)d_in[6];  const float* bd3 = (const float*)d_in[7];
    const float* W_ih = (const float*)d_in[8]; const float* W_hh = (const float*)d_in[9];
    const float* b_ih = (const float*)d_in[10]; const float* b_hh = (const float*)d_in[11];
    const float* Wm1 = (const float*)d_in[12]; const float* bm1 = (const float*)d_in[13];
    const float* Wm2 = (const float*)d_in[14]; const float* bm2 = (const float*)d_in[15];
    const float* Wm3 = (const float*)d_in[16]; const float* bm3 = (const float*)d_in[17];
    float* out = (float*)d_out;

    float *t1p, *t2p, *h0p, *Hallp, *bigp, *gibp;
    cudaGetSymbolAddress((void**)&t1p, g_t1);
    cudaGetSymbolAddress((void**)&t2p, g_t2);
    cudaGetSymbolAddress((void**)&h0p, g_h0);
    cudaGetSymbolAddress((void**)&Hallp, g_Hall);
    cudaGetSymbolAddress((void**)&bigp, g_big);
    cudaGetSymbolAddress((void**)&gibp, g_gib);

    dim3 thr(256);

    // BOS input-gate vector (includes b_ih)
    gib_kernel<<<(3 * Hd + 255) / 256, 256>>>(W_ih, b_ih, gibp);

    // gi chunk 0: t in [1, 63]
    gi_gemm_kernel<<<dim3((3 * Hd) / 128, GIROWS / 128), thr>>>(target, W_ih, b_ih, bigp, 1);

    // initial hidden MLP
    gemm_nt_kernel<true><<<dim3(Hd / 128, Bsz / 128), thr>>>(latent, Wd1, bd1, t1p, Bsz, Hd, LAT);
    gemm_nt_kernel<true><<<dim3(Hd / 128, Bsz / 128), thr>>>(t1p, Wd2, bd2, t2p, Bsz, Hd, Hd);
    gemm_nt_kernel<false><<<dim3(Hd / 128, Bsz / 128), thr>>>(t2p, Wd3, bd3, h0p, Bsz, Hd, Hd);

    // sequential GRU steps: t=0 (BOS) .. 63 use chunk 0
    for (int t = 0; t <= TCHUNK; t++) {
        gru_step_kernel<<<dim3(Hd / 64, Bsz / 64), thr>>>(W_hh, b_hh, t, t - 1);
    }
    // gi chunk 1: t in [64, 126] (overwrites chunk 0 — stream order makes this safe)
    gi_gemm_kernel<<<dim3((3 * Hd) / 128, GIROWS / 128), thr>>>(target, W_ih, b_ih, bigp, 1 + TCHUNK);
    for (int t = TCHUNK + 1; t < NSTEP; t++) {
        gru_step_kernel<<<dim3(Hd / 64, Bsz / 64), thr>>>(W_hh, b_hh, t, t - 1 - TCHUNK);
    }

    // batched decoder head over all (t, b) rows; P1 aliases the gi buffer (gi is dead)
    gemm_nt_kernel<true><<<dim3(Hd / 128, (NSTEP * Bsz) / 128), thr>>>(
        Hallp, Wm1, bm1, bigp, NSTEP * Bsz, Hd, Hd);
    decode_tail_kernel<<<dim3((NSTEP * Bsz) / 64), thr>>>(bigp, Wm2, bm2, Wm3, bm3, out);

    // BOS column (out[:, 0, :])
    bos_kernel<<<(Bsz * Ad + 255) / 256, 256>>>(out);
}